// round 16
// baseline (speedup 1.0000x reference)
#include <cuda_runtime.h>
#include <cuda_bf16.h>

// WaveletTransform: 3-level low-pass pyramid on x[8,32,512,512] fp32.
// out = x, except per-channel:
//   out[0:256,0:256] = down2x(conv3x3(x[0:512,0:512]))        (level 0)
//   out[0:128,0:128] = down2x(conv3x3(level0 result[0:256]^2)) (level 1)
//   out[0: 64,0: 64] = down2x(conv3x3(level1 result[0:128]^2)) (level 2)
// conv = outer([.25,.5,.25],[.25,.5,.25]), zero-padded 'same', even-index
// downsample (center 2i,2j -> taps 2i-1..2i+1).
//
// R16: SINGLE kernel, "last-CTA-does-the-tail":
//  - 64 CTAs per channel do the R3-shape K1 work (fused copy + level-0).
//  - Each CTA: __threadfence(); atomicAdd(g_cnt[bc],1). The CTA seeing
//    old%64==63 (all of this channel's level-0 stores complete AND L2-hot)
//    runs levels 1+2 for the channel as 4 SEQUENTIAL strips (17KB smem).
//    Sequential strips are race-free: strip k reads level-0 rows >= 64k-3,
//    prior strips wrote only rows < 32k, and 64k-3 >= 32k for k>=1.
//  - mod-64 counter => no reset needed across graph replays; identical
//    work every launch.
//  - Kills K23's 64MB DRAM re-read (now L2 hits) + the second launch.

#define BC_TOTAL (8 * 32)
#define H0 512
#define W0C 512

#define L1S 132                          // 128 + 4 floats pad
#define L1_ROWS 33

__device__ unsigned int g_cnt[BC_TOTAL];   // zero-init at module load

__device__ __forceinline__ float hfilt(float a, float b, float c) {
    return 0.25f * a + 0.5f * b + 0.25f * c;
}

__global__ void __launch_bounds__(256) wavelet_fused(
    const float* __restrict__ x, float* __restrict__ out)
{
    __shared__ float l1[L1_ROWS * L1S];
    __shared__ unsigned int s_old;

    const int tid  = threadIdx.x;
    const int j4   = tid & 127;                  // 0..127 (col/4)
    const int sub  = tid >> 7;                   // 0..1
    const int base = blockIdx.y * 8 + sub * 4;   // first of 4 rows
    const int bc   = blockIdx.z;

    const float* xp = x   + (size_t)bc * H0 * W0C;
    float*       op = out + (size_t)bc * H0 * W0C;

    // ======================= K1 work (exact R3 shape) =======================
    if (base < 256 && j4 < 64) {
        #pragma unroll
        for (int it = 0; it < 4; it++) {
            const int i  = base + it;
            const int r0 = 2 * i - 1;
            float acc0 = 0.f, acc1 = 0.f, acc2 = 0.f, acc3 = 0.f;
            #pragma unroll
            for (int a = 0; a < 3; a++) {
                const int r = r0 + a;            // <= 511
                if (r < 0) continue;             // warp-uniform
                const float wr = (a == 1) ? 0.5f : 0.25f;
                const float* row = xp + (size_t)r * W0C;
                const float4* rv = reinterpret_cast<const float4*>(row) + 2 * j4;
                float4 p0 = rv[0];
                float4 p1 = rv[1];
                float left = __shfl_up_sync(0xFFFFFFFFu, p1.w, 1);
                if ((j4 & 31) == 0)
                    left = (j4 == 0) ? 0.f : row[8 * j4 - 1];
                acc0 += wr * hfilt(left, p0.x, p0.y);
                acc1 += wr * hfilt(p0.y, p0.z, p0.w);
                acc2 += wr * hfilt(p0.w, p1.x, p1.y);
                acc3 += wr * hfilt(p1.y, p1.z, p1.w);
            }
            *reinterpret_cast<float4*>(op + (size_t)i * W0C + 4 * j4) =
                make_float4(acc0, acc1, acc2, acc3);
        }
    } else {
        float4 v[4];
        #pragma unroll
        for (int it = 0; it < 4; it++)
            v[it] = *(reinterpret_cast<const float4*>(
                          xp + (size_t)(base + it) * W0C) + j4);
        #pragma unroll
        for (int it = 0; it < 4; it++)
            __stcs(reinterpret_cast<float4*>(
                       op + (size_t)(base + it) * W0C) + j4, v[it]);
    }

    // ============ completion detection: last CTA of this channel ============
    __threadfence();            // order this thread's out-stores GPU-wide
    __syncthreads();            // all threads of CTA fenced
    if (tid == 0)
        s_old = atomicAdd(&g_cnt[bc], 1u);
    __syncthreads();
    if ((s_old & 63u) != 63u)
        return;
    __threadfence();            // acquire: siblings' stores now visible

    // ================= tail: levels 1+2, 4 sequential strips =================
    const int lane = tid & 31;
    const int wid  = tid >> 5;                  // 0..7

    for (int k = 0; k < 4; k++) {
        // ---- Phase 1: level-1 conv rows 32k-1..32k+31 -> smem ----
        #pragma unroll
        for (int t = 0; t < 5; t++) {
            const int r_local = 8 * t + wid;    // 0..39; valid <= 32
            if (r_local <= 32) {
                const int r1 = 32 * k - 1 + r_local;   // -1..127
                float acc0 = 0.f, acc1 = 0.f, acc2 = 0.f, acc3 = 0.f;
                if (r1 >= 0) {                  // warp-uniform
                    const int r0v = 2 * r1 - 1;
                    #pragma unroll
                    for (int a = 0; a < 3; a++) {
                        const int r = r0v + a;  // <= 255
                        if (r < 0) continue;    // warp-uniform
                        const float wr = (a == 1) ? 0.5f : 0.25f;
                        const float* row = op + (size_t)r * W0C;
                        const float4* rv =
                            reinterpret_cast<const float4*>(row) + 2 * lane;
                        float4 p0 = rv[0];
                        float4 p1 = rv[1];
                        float left = __shfl_up_sync(0xFFFFFFFFu, p1.w, 1);
                        if (lane == 0) left = 0.f;
                        acc0 += wr * hfilt(left, p0.x, p0.y);
                        acc1 += wr * hfilt(p0.y, p0.z, p0.w);
                        acc2 += wr * hfilt(p0.w, p1.x, p1.y);
                        acc3 += wr * hfilt(p1.y, p1.z, p1.w);
                    }
                }
                *reinterpret_cast<float4*>(&l1[r_local * L1S + 4 * lane]) =
                    make_float4(acc0, acc1, acc2, acc3);   // zeros if r1 < 0
            }
        }
        __syncthreads();

        // ---- Phase 2a: level-2 rows 16k..16k+15, one float4/thread ----
        {
            const int i2l = tid >> 4;           // 0..15
            const int g   = tid & 15;           // float4 col group
            float acc0 = 0.f, acc1 = 0.f, acc2 = 0.f, acc3 = 0.f;
            #pragma unroll
            for (int a = 0; a < 3; a++) {
                const int loc = 2 * i2l + a;    // 0..31 (local row -1 = zeros)
                const float* row = &l1[loc * L1S];
                float4 p0 = *reinterpret_cast<const float4*>(row + 8 * g);
                float4 p1 = *reinterpret_cast<const float4*>(row + 8 * g + 4);
                const float wr = (a == 1) ? 0.5f : 0.25f;
                float left = __shfl_up_sync(0xFFFFFFFFu, p1.w, 1);
                if (g == 0) left = 0.f;
                acc0 += wr * hfilt(left, p0.x, p0.y);
                acc1 += wr * hfilt(p0.y, p0.z, p0.w);
                acc2 += wr * hfilt(p0.w, p1.x, p1.y);
                acc3 += wr * hfilt(p1.y, p1.z, p1.w);
            }
            __stcs(reinterpret_cast<float4*>(
                       op + (size_t)(16 * k + tid / 16) * W0C + 4 * g),
                   make_float4(acc0, acc1, acc2, acc3));
        }

        // ---- Phase 2b: copy level-1 rows 32k..32k+31 outside inner 64^2 ----
        #pragma unroll
        for (int q = 0; q < 4; q++) {
            const int idx = tid + 256 * q;      // 0..1023
            const int row = idx >> 5;           // 0..31
            const int jc  = idx & 31;           // 0..31
            const int i   = 32 * k + row;       // 0..127
            if (i >= 64 || jc >= 16) {
                float4 v = *reinterpret_cast<const float4*>(
                               &l1[(row + 1) * L1S + 4 * jc]);
                __stcs(reinterpret_cast<float4*>(
                           op + (size_t)i * W0C + 4 * jc), v);
            }
        }
        __syncthreads();   // protect smem before next strip overwrites it
    }
}

extern "C" void kernel_launch(void* const* d_in, const int* in_sizes, int n_in,
                              void* d_out, int out_size)
{
    (void)in_sizes; (void)n_in; (void)out_size;
    const float* x = (const float*)d_in[0];
    float* out = (float*)d_out;

    wavelet_fused<<<dim3(1, 64, BC_TOTAL), dim3(256)>>>(x, out);
}

// round 17
// speedup vs baseline: 1.1203x; 1.1203x over previous
#include <cuda_runtime.h>
#include <cuda_bf16.h>
#include <cstdint>

// WaveletTransform: 3-level low-pass pyramid on x[8,32,512,512] fp32.
// out = x, except per-channel:
//   out[0:256,0:256] = down2x(conv3x3(x[0:512,0:512]))        (level 0)
//   out[0:128,0:128] = down2x(conv3x3(level0 result[0:256]^2)) (level 1)
//   out[0: 64,0: 64] = down2x(conv3x3(level1 result[0:128]^2)) (level 2)
// conv = outer([.25,.5,.25],[.25,.5,.25]), zero-padded 'same', even-index
// downsample (center 2i,2j -> taps 2i-1..2i+1).
//
// R17: SINGLE kernel, producer-consumer in one grid (1,68,256):
//  y<64  : work CTA, exact R3 K1 shape (fused copy + level-0);
//          release: __threadfence + atomicAdd(g_work[bc]).
//  y>=64 : tail CTA = ONE K23 strip (k=y-64), 4 parallel per channel.
//          Spins (acquire + nanosleep) until g_work[bc] shows 64 new
//          arrivals; reads level-0 (L2-hot: just written) into smem;
//          WAR barrier among the 4 strips via second monotone counter
//          g_rdy; then writes level-2 + level-1 copy region (.cs).
//  All counters monotone; targets from returned olds -> replay-safe.
//  Kills: 2nd launch, K23's 64MB DRAM re-read, cluster convoy.
//  (R16's serial 4-strip tail wrecked wave balance; tails now parallel.)

#define BC_TOTAL (8 * 32)
#define H0 512
#define W0C 512

#define L1S 132                          // 128 + 4 floats pad
#define L1_ROWS 33

__device__ unsigned int g_work[BC_TOTAL];   // +64 per channel per launch
__device__ unsigned int g_tail[BC_TOTAL];   // +4  per channel per launch
__device__ unsigned int g_rdy [BC_TOTAL];   // +4  per channel per launch

__device__ __forceinline__ float hfilt(float a, float b, float c) {
    return 0.25f * a + 0.5f * b + 0.25f * c;
}

__device__ __forceinline__ unsigned int ld_acq(const unsigned int* p) {
    unsigned int v;
    asm volatile("ld.acquire.gpu.u32 %0, [%1];" : "=r"(v) : "l"(p) : "memory");
    return v;
}

__global__ void __launch_bounds__(256) wavelet_fused(
    const float* __restrict__ x, float* __restrict__ out)
{
    __shared__ float l1[L1_ROWS * L1S];

    const int tid = threadIdx.x;
    const int y   = blockIdx.y;                  // 0..67
    const int bc  = blockIdx.z;

    const float* xp = x   + (size_t)bc * H0 * W0C;
    float*       op = out + (size_t)bc * H0 * W0C;

    if (y < 64) {
        // =================== work CTA: exact R3 K1 shape ===================
        const int j4   = tid & 127;              // 0..127 (col/4)
        const int sub  = tid >> 7;               // 0..1
        const int base = y * 8 + sub * 4;        // first of 4 rows

        if (base < 256 && j4 < 64) {
            #pragma unroll
            for (int it = 0; it < 4; it++) {
                const int i  = base + it;
                const int r0 = 2 * i - 1;
                float acc0 = 0.f, acc1 = 0.f, acc2 = 0.f, acc3 = 0.f;
                #pragma unroll
                for (int a = 0; a < 3; a++) {
                    const int r = r0 + a;        // <= 511
                    if (r < 0) continue;         // warp-uniform
                    const float wr = (a == 1) ? 0.5f : 0.25f;
                    const float* row = xp + (size_t)r * W0C;
                    const float4* rv =
                        reinterpret_cast<const float4*>(row) + 2 * j4;
                    float4 p0 = rv[0];
                    float4 p1 = rv[1];
                    float left = __shfl_up_sync(0xFFFFFFFFu, p1.w, 1);
                    if ((j4 & 31) == 0)
                        left = (j4 == 0) ? 0.f : row[8 * j4 - 1];
                    acc0 += wr * hfilt(left, p0.x, p0.y);
                    acc1 += wr * hfilt(p0.y, p0.z, p0.w);
                    acc2 += wr * hfilt(p0.w, p1.x, p1.y);
                    acc3 += wr * hfilt(p1.y, p1.z, p1.w);
                }
                *reinterpret_cast<float4*>(op + (size_t)i * W0C + 4 * j4) =
                    make_float4(acc0, acc1, acc2, acc3);
            }
        } else {
            float4 v[4];
            #pragma unroll
            for (int it = 0; it < 4; it++)
                v[it] = *(reinterpret_cast<const float4*>(
                              xp + (size_t)(base + it) * W0C) + j4);
            #pragma unroll
            for (int it = 0; it < 4; it++)
                __stcs(reinterpret_cast<float4*>(
                           op + (size_t)(base + it) * W0C) + j4, v[it]);
        }

        // release: my stores are visible before the count ticks
        __threadfence();
        __syncthreads();
        if (tid == 0)
            atomicAdd(&g_work[bc], 1u);
        return;
    }

    // ===================== tail CTA: one K23 strip =====================
    const int k    = y - 64;                    // strip 0..3
    const int lane = tid & 31;
    const int wid  = tid >> 5;                  // 0..7

    // wait for all 64 work CTAs of this channel (monotone, replay-safe)
    if (tid == 0) {
        const unsigned int t_old  = atomicAdd(&g_tail[bc], 1u);
        const unsigned int rep    = t_old >> 2;          // launch index
        const unsigned int target = 64u * (rep + 1u);
        while (ld_acq(&g_work[bc]) < target)
            __nanosleep(128);
    }
    __syncthreads();

    // ---- Phase 1: level-1 conv rows 32k-1..32k+31 -> smem (L2-hot reads) ----
    #pragma unroll
    for (int t = 0; t < 5; t++) {
        const int r_local = 8 * t + wid;        // 0..39; valid <= 32
        if (r_local <= 32) {
            const int r1 = 32 * k - 1 + r_local;   // -1..127
            float acc0 = 0.f, acc1 = 0.f, acc2 = 0.f, acc3 = 0.f;
            if (r1 >= 0) {                      // warp-uniform
                const int r0v = 2 * r1 - 1;
                #pragma unroll
                for (int a = 0; a < 3; a++) {
                    const int r = r0v + a;      // <= 255
                    if (r < 0) continue;        // warp-uniform
                    const float wr = (a == 1) ? 0.5f : 0.25f;
                    const float* row = op + (size_t)r * W0C;
                    const float4* rv =
                        reinterpret_cast<const float4*>(row) + 2 * lane;
                    float4 p0 = rv[0];
                    float4 p1 = rv[1];
                    float left = __shfl_up_sync(0xFFFFFFFFu, p1.w, 1);
                    if (lane == 0) left = 0.f;
                    acc0 += wr * hfilt(left, p0.x, p0.y);
                    acc1 += wr * hfilt(p0.y, p0.z, p0.w);
                    acc2 += wr * hfilt(p0.w, p1.x, p1.y);
                    acc3 += wr * hfilt(p1.y, p1.z, p1.w);
                }
            }
            *reinterpret_cast<float4*>(&l1[r_local * L1S + 4 * lane]) =
                make_float4(acc0, acc1, acc2, acc3);   // zeros when r1 < 0
        }
    }
    __syncthreads();   // all phase-1 level-0 reads consumed; smem complete

    // ---- Phase 2a compute into registers (smem-only) ----
    const int i2l = tid >> 4;                   // 0..15
    const int g   = tid & 15;                   // float4 col group
    float4 r2a = make_float4(0.f, 0.f, 0.f, 0.f);
    #pragma unroll
    for (int a = 0; a < 3; a++) {
        const int loc = 2 * i2l + a;            // 0..31 (local row -1 = zeros)
        const float* row = &l1[loc * L1S];
        float4 p0 = *reinterpret_cast<const float4*>(row + 8 * g);
        float4 p1 = *reinterpret_cast<const float4*>(row + 8 * g + 4);
        const float wr = (a == 1) ? 0.5f : 0.25f;
        float left = __shfl_up_sync(0xFFFFFFFFu, p1.w, 1);
        if (g == 0) left = 0.f;
        r2a.x += wr * hfilt(left, p0.x, p0.y);
        r2a.y += wr * hfilt(p0.y, p0.z, p0.w);
        r2a.z += wr * hfilt(p0.w, p1.x, p1.y);
        r2a.w += wr * hfilt(p1.y, p1.z, p1.w);
    }

    // ---- WAR barrier among the 4 strips of this channel ----
    if (tid == 0) {
        const unsigned int r_old  = atomicAdd(&g_rdy[bc], 1u);
        const unsigned int target = (r_old & ~3u) + 4u;
        while (ld_acq(&g_rdy[bc]) < target)
            __nanosleep(64);
    }
    __syncthreads();

    // ---- Phase 2a store: level-2 rows 16k..16k+15 ----
    __stcs(reinterpret_cast<float4*>(
               op + (size_t)(16 * k + i2l) * W0C + 4 * g), r2a);

    // ---- Phase 2b: copy level-1 rows 32k..32k+31 outside inner 64^2 ----
    #pragma unroll
    for (int q = 0; q < 4; q++) {
        const int idx = tid + 256 * q;          // 0..1023
        const int row = idx >> 5;               // 0..31
        const int jc  = idx & 31;               // 0..31
        const int i   = 32 * k + row;           // 0..127
        if (i >= 64 || jc >= 16) {
            float4 v = *reinterpret_cast<const float4*>(
                           &l1[(row + 1) * L1S + 4 * jc]);
            __stcs(reinterpret_cast<float4*>(
                       op + (size_t)i * W0C + 4 * jc), v);
        }
    }
}

extern "C" void kernel_launch(void* const* d_in, const int* in_sizes, int n_in,
                              void* d_out, int out_size)
{
    (void)in_sizes; (void)n_in; (void)out_size;
    const float* x = (const float*)d_in[0];
    float* out = (float*)d_out;

    wavelet_fused<<<dim3(1, 68, BC_TOTAL), dim3(256)>>>(x, out);
}